// round 3
// baseline (speedup 1.0000x reference)
#include <cuda_runtime.h>

// Shapes (fixed): B=8, H=8, N=2048, C=64  -> BH=64 head-batches
#define NTOK 2048
#define CDIM 64
#define NBH  64

__device__ float g_q[NBH * NTOK * CDIM];
__device__ float g_k[NBH * NTOK * CDIM];
__device__ float g_v[NBH * NTOK * CDIM];

typedef unsigned long long u64;
typedef ulonglong2 ull2;

__device__ __forceinline__ u64 pk2(float lo, float hi) {
    u64 r; asm("mov.b64 %0,{%1,%2};" : "=l"(r) : "f"(lo), "f"(hi)); return r;
}
__device__ __forceinline__ void up2(u64 v, float &lo, float &hi) {
    asm("mov.b64 {%0,%1},%2;" : "=f"(lo), "=f"(hi) : "l"(v));
}
__device__ __forceinline__ u64 f2fma(u64 a, u64 b, u64 c) {
    u64 d; asm("fma.rn.f32x2 %0,%1,%2,%3;" : "=l"(d) : "l"(a), "l"(b), "l"(c)); return d;
}
__device__ __forceinline__ u64 f2mul(u64 a, u64 b) {
    u64 d; asm("mul.rn.f32x2 %0,%1,%2;" : "=l"(d) : "l"(a), "l"(b)); return d;
}

// ---------------------------------------------------------------------------
// Kernel 1: fused QKV projection (unchanged).
// ---------------------------------------------------------------------------
__global__ void __launch_bounds__(256) qkv_kernel(const float* __restrict__ x,
                                                  const float* __restrict__ W) {
    extern __shared__ float Ws[];
    for (int i = threadIdx.x; i < 192 * 64; i += 256) Ws[i] = W[i];
    __syncthreads();

    int row = blockIdx.x * 256 + threadIdx.x;
    float xr[64];
    const float4* xp = (const float4*)(x + (size_t)row * 64);
#pragma unroll
    for (int c4 = 0; c4 < 16; c4++) {
        float4 t = xp[c4];
        xr[c4 * 4 + 0] = t.x; xr[c4 * 4 + 1] = t.y;
        xr[c4 * 4 + 2] = t.z; xr[c4 * 4 + 3] = t.w;
    }

    for (int d = 0; d < 192; d += 4) {
        float a0 = 0.f, a1 = 0.f, a2 = 0.f, a3 = 0.f;
        const float* w0 = &Ws[d * 64];
#pragma unroll
        for (int c = 0; c < 64; c++) {
            float xv = xr[c];
            a0 = fmaf(xv, w0[c],        a0);
            a1 = fmaf(xv, w0[64 + c],   a1);
            a2 = fmaf(xv, w0[128 + c],  a2);
            a3 = fmaf(xv, w0[192 + c],  a3);
        }
        float* dst = (d < 64) ? g_q : ((d < 128) ? g_k : g_v);
        int dd = d & 63;
        *(float4*)&dst[(size_t)row * 64 + dd] = make_float4(a0, a1, a2, a3);
    }
}

// ---------------------------------------------------------------------------
// Kernel 2: flash attention. BM=128, BN=64, 256 threads, 2 CTAs/SM.
// Thread grid: ty = tid>>3 (32 row-groups of 4), tx = tid&7 (8 col-groups of 8).
// Microtile 4x8 in both GEMM phases (acc as 4x4 u64, packed FFMA2).
// smem tiles c-major (Qt,Kt) / k-major (Pt) with 3-bit XOR swizzle on the
// row-group index; V row-major. Total 96 KB -> 2 CTAs per SM.
// ---------------------------------------------------------------------------
#define BM 128
#define BN 64
#define QT_OFF 0                       // Qt[c][128]  c=0..63
#define KT_OFF (64 * 128)              // Kt[c][64]
#define VS_OFF (KT_OFF + 64 * 64)      // Vs[k][64]
#define PT_OFF (VS_OFF + 64 * 64)      // Pt[k][128]
#define SMEM_FLOATS (PT_OFF + 64 * 128)  // 24576 floats
#define SMEM_BYTES  (SMEM_FLOATS * 4)    // 98304

__global__ void __launch_bounds__(256, 2) attn_kernel(float* __restrict__ out) {
    extern __shared__ float sm[];

    const int bh = blockIdx.y;
    const int m0 = blockIdx.x * BM;
    const float* qg = g_q + (size_t)bh * NTOK * CDIM;
    const float* kg = g_k + (size_t)bh * NTOK * CDIM;
    const float* vg = g_v + (size_t)bh * NTOK * CDIM;

    const int tid = threadIdx.x;
    const int ty = tid >> 3;   // 0..31 : 4 rows each
    const int tx = tid & 7;    // 0..7  : 8 cols each

    // ---- load Q tile -> Qt[c][r] swizzled, pre-scaled by 1/8 ----
#pragma unroll
    for (int it = 0; it < 8; it++) {
        int fi = it * 256 + tid;            // 0..2047
        int r  = fi >> 4;                   // 0..127
        int c4 = (fi & 15) << 2;            // 0..60
        float4 t = *(const float4*)&qg[(size_t)(m0 + r) * 64 + c4];
        int sw = (c4 >> 2) & 7;
        int base = QT_OFF + c4 * 128 + ((((r >> 2) ^ sw)) << 2) + (r & 3);
        sm[base]       = t.x * 0.125f;
        sm[base + 128] = t.y * 0.125f;
        sm[base + 256] = t.z * 0.125f;
        sm[base + 384] = t.w * 0.125f;
    }

    u64 oacc[4][4];
    float mi[4], li[4];
#pragma unroll
    for (int i = 0; i < 4; i++) {
#pragma unroll
        for (int p = 0; p < 4; p++) oacc[i][p] = 0ull;
        mi[i] = -1e30f; li[i] = 0.f;
    }

    for (int kt = 0; kt < NTOK / BN; kt++) {
        const int k0 = kt * BN;

        // ---- prefetch K/V tile to registers (overlaps prev-phase tail) ----
        float4 kr[4], vr[4];
#pragma unroll
        for (int it = 0; it < 4; it++) {
            int fi = it * 256 + tid;        // 0..1023
            int r  = fi >> 4;               // 0..63
            int c4 = (fi & 15) << 2;
            kr[it] = *(const float4*)&kg[(size_t)(k0 + r) * 64 + c4];
            vr[it] = *(const float4*)&vg[(size_t)(k0 + r) * 64 + c4];
        }
        __syncthreads();   // prev iteration done reading Kt/Vs/Pt

        // ---- store tiles: Kt transposed+swizzled, Vs row-major ----
#pragma unroll
        for (int it = 0; it < 4; it++) {
            int fi = it * 256 + tid;
            int r  = fi >> 4;
            int c4 = (fi & 15) << 2;
            int sw = (c4 >> 2) & 7;
            int base = KT_OFF + c4 * 64 + ((((r >> 2) ^ sw)) << 2) + (r & 3);
            sm[base]       = kr[it].x;
            sm[base +  64] = kr[it].y;
            sm[base + 128] = kr[it].z;
            sm[base + 192] = kr[it].w;
            *(float4*)&sm[VS_OFF + r * 64 + c4] = vr[it];
        }
        __syncthreads();

        // ---- S = Q K^T : rows ty*4+i, cols tx*8+j ----
        u64 acc[4][4];
#pragma unroll
        for (int i = 0; i < 4; i++)
#pragma unroll
            for (int p = 0; p < 4; p++) acc[i][p] = 0ull;

#pragma unroll 2
        for (int cb = 0; cb < 16; cb++) {
            const int sw = cb & 7;
            const float* qp = &sm[QT_OFF + cb * 4 * 128 + ((ty ^ sw) << 2)];
            const float* kp = &sm[KT_OFF + cb * 4 * 64];
            const int ka0 = ((2 * tx) ^ sw) << 2;
            const int ka1 = ((2 * tx + 1) ^ sw) << 2;
#pragma unroll
            for (int cc = 0; cc < 4; cc++) {
                float4 qa = *(const float4*)(qp + cc * 128);
                ull2 kb0 = *(const ull2*)(kp + cc * 64 + ka0);
                ull2 kb1 = *(const ull2*)(kp + cc * 64 + ka1);
                u64 qb;
                qb = pk2(qa.x, qa.x);
                acc[0][0] = f2fma(qb, kb0.x, acc[0][0]);
                acc[0][1] = f2fma(qb, kb0.y, acc[0][1]);
                acc[0][2] = f2fma(qb, kb1.x, acc[0][2]);
                acc[0][3] = f2fma(qb, kb1.y, acc[0][3]);
                qb = pk2(qa.y, qa.y);
                acc[1][0] = f2fma(qb, kb0.x, acc[1][0]);
                acc[1][1] = f2fma(qb, kb0.y, acc[1][1]);
                acc[1][2] = f2fma(qb, kb1.x, acc[1][2]);
                acc[1][3] = f2fma(qb, kb1.y, acc[1][3]);
                qb = pk2(qa.z, qa.z);
                acc[2][0] = f2fma(qb, kb0.x, acc[2][0]);
                acc[2][1] = f2fma(qb, kb0.y, acc[2][1]);
                acc[2][2] = f2fma(qb, kb1.x, acc[2][2]);
                acc[2][3] = f2fma(qb, kb1.y, acc[2][3]);
                qb = pk2(qa.w, qa.w);
                acc[3][0] = f2fma(qb, kb0.x, acc[3][0]);
                acc[3][1] = f2fma(qb, kb0.y, acc[3][1]);
                acc[3][2] = f2fma(qb, kb1.x, acc[3][2]);
                acc[3][3] = f2fma(qb, kb1.y, acc[3][3]);
            }
        }

        float s[4][8];
#pragma unroll
        for (int i = 0; i < 4; i++)
#pragma unroll
            for (int p = 0; p < 4; p++)
                up2(acc[i][p], s[i][2 * p], s[i][2 * p + 1]);

        // ---- online softmax: full row lives in-warp across tx (lane bits 0..2) ----
        float alpha[4];
#pragma unroll
        for (int i = 0; i < 4; i++) {
            float m = s[i][0];
#pragma unroll
            for (int j = 1; j < 8; j++) m = fmaxf(m, s[i][j]);
            m = fmaxf(m, __shfl_xor_sync(0xffffffffu, m, 1));
            m = fmaxf(m, __shfl_xor_sync(0xffffffffu, m, 2));
            m = fmaxf(m, __shfl_xor_sync(0xffffffffu, m, 4));
            float mn = fmaxf(mi[i], m);
            alpha[i] = __expf(mi[i] - mn);
            mi[i] = mn;
            float r = 0.f;
#pragma unroll
            for (int j = 0; j < 8; j++) { s[i][j] = __expf(s[i][j] - mn); r += s[i][j]; }
            r += __shfl_xor_sync(0xffffffffu, r, 1);
            r += __shfl_xor_sync(0xffffffffu, r, 2);
            r += __shfl_xor_sync(0xffffffffu, r, 4);
            li[i] = li[i] * alpha[i] + r;
        }

        // rescale O
#pragma unroll
        for (int i = 0; i < 4; i++) {
            u64 ab = pk2(alpha[i], alpha[i]);
#pragma unroll
            for (int p = 0; p < 4; p++) oacc[i][p] = f2mul(oacc[i][p], ab);
        }

        // publish P transposed+swizzled: Pt[k = tx*8+j][rows ty*4..+3]
#pragma unroll
        for (int j = 0; j < 8; j++) {
            int k = tx * 8 + j;
            int sw = (k >> 2) & 7;
            *(float4*)&sm[PT_OFF + k * 128 + ((ty ^ sw) << 2)] =
                make_float4(s[0][j], s[1][j], s[2][j], s[3][j]);
        }
        __syncthreads();

        // ---- O += P V : rows ty*4+i, cols tx*8+j ----
#pragma unroll 2
        for (int kb = 0; kb < 16; kb++) {
            const int sw = kb & 7;
            const float* pp = &sm[PT_OFF + kb * 4 * 128 + ((ty ^ sw) << 2)];
            const float* vp = &sm[VS_OFF + kb * 4 * 64 + tx * 8];
#pragma unroll
            for (int kc = 0; kc < 4; kc++) {
                float4 pa = *(const float4*)(pp + kc * 128);
                ull2 vb0 = *(const ull2*)(vp + kc * 64);
                ull2 vb1 = *(const ull2*)(vp + kc * 64 + 4);
                u64 pb;
                pb = pk2(pa.x, pa.x);
                oacc[0][0] = f2fma(pb, vb0.x, oacc[0][0]);
                oacc[0][1] = f2fma(pb, vb0.y, oacc[0][1]);
                oacc[0][2] = f2fma(pb, vb1.x, oacc[0][2]);
                oacc[0][3] = f2fma(pb, vb1.y, oacc[0][3]);
                pb = pk2(pa.y, pa.y);
                oacc[1][0] = f2fma(pb, vb0.x, oacc[1][0]);
                oacc[1][1] = f2fma(pb, vb0.y, oacc[1][1]);
                oacc[1][2] = f2fma(pb, vb1.x, oacc[1][2]);
                oacc[1][3] = f2fma(pb, vb1.y, oacc[1][3]);
                pb = pk2(pa.z, pa.z);
                oacc[2][0] = f2fma(pb, vb0.x, oacc[2][0]);
                oacc[2][1] = f2fma(pb, vb0.y, oacc[2][1]);
                oacc[2][2] = f2fma(pb, vb1.x, oacc[2][2]);
                oacc[2][3] = f2fma(pb, vb1.y, oacc[2][3]);
                pb = pk2(pa.w, pa.w);
                oacc[3][0] = f2fma(pb, vb0.x, oacc[3][0]);
                oacc[3][1] = f2fma(pb, vb0.y, oacc[3][1]);
                oacc[3][2] = f2fma(pb, vb1.x, oacc[3][2]);
                oacc[3][3] = f2fma(pb, vb1.y, oacc[3][3]);
            }
        }
    }

    // ---- epilogue: normalize + head-mixing shuffle ----
    // cols cc = tx*8 + j  ->  hp = tx, jp = j  (contiguous float4 stores)
    const int b = bh >> 3, h = bh & 7;
#pragma unroll
    for (int i = 0; i < 4; i++) {
        float inv = 1.0f / li[i];
        int n = m0 + ty * 4 + i;
        float ov[8];
        up2(oacc[i][0], ov[0], ov[1]);
        up2(oacc[i][1], ov[2], ov[3]);
        up2(oacc[i][2], ov[4], ov[5]);
        up2(oacc[i][3], ov[6], ov[7]);
        float* dst = &out[(((size_t)(b * 8 + tx) * NTOK + n) << 6) + h * 8];
        *(float4*)dst       = make_float4(ov[0] * inv, ov[1] * inv, ov[2] * inv, ov[3] * inv);
        *(float4*)(dst + 4) = make_float4(ov[4] * inv, ov[5] * inv, ov[6] * inv, ov[7] * inv);
    }
}

// ---------------------------------------------------------------------------
extern "C" void kernel_launch(void* const* d_in, const int* in_sizes, int n_in,
                              void* d_out, int out_size) {
    const float* x = (const float*)d_in[0];      // [8,8,2048,64]
    const float* W = (const float*)d_in[1];      // [192,64]
    float* out = (float*)d_out;                  // [8,8,2048,64]

    cudaFuncSetAttribute(qkv_kernel,  cudaFuncAttributeMaxDynamicSharedMemorySize, 49152);
    cudaFuncSetAttribute(attn_kernel, cudaFuncAttributeMaxDynamicSharedMemorySize, SMEM_BYTES);

    qkv_kernel<<<(NBH * NTOK) / 256, 256, 49152>>>(x, W);
    attn_kernel<<<dim3(NTOK / BM, NBH), 256, SMEM_BYTES>>>(out);
}